// round 15
// baseline (speedup 1.0000x reference)
#include <cuda_runtime.h>

// ---------------------------------------------------------------------------
// SpanRepresentationLayer on GB300.
//
// Factorization: out[b,(s,e),t,h] = P[b,s,t,h] + Q[b,e,t,h], where
//   P[b,s,t,h] = sum_c hid[b,s,c] * W[t,h,c]       + bias[t,h]
//   Q[b,e,t,h] = sum_c hid[b,e,c] * W[t,h,256+c]
// Kernel 1: fp32 SGEMM  X[8192,256] x Wt[256,2048] -> PQ scratch (64 MB)
//           column j = pq*1024 + t*256 + h ; Wt row j is contiguous in W.
// Kernel 2: expansion   out[row] = P[s] + Q[e]  (pure bandwidth, streaming st)
// ---------------------------------------------------------------------------

#define HID     256
#define SEQ     1024
#define NBATCH  8
#define NT      4
#define NSPAN   12222      // sum_s min(12, 1024-s)
#define NFULL   12156      // spans with s <= 1012 (12 each)
#define KDIM    256
#define NCOL    2048       // 2 * NT * HID  (pq, t, h)
#define MROWS   (NBATCH * SEQ)   // 8192

// 64 MB scratch: PQ[m][j], m = b*1024+s, j = pq*1024 + t*256 + h
__device__ float g_PQ[(size_t)MROWS * NCOL];

// ------------------------------ GEMM ---------------------------------------
#define BM 128
#define BN 128
#define BK 16
#define TM 8
#define TN 8
#define PAD 8   // keeps float4 smem reads 16B-aligned (stride 136 floats)

__global__ void __launch_bounds__(256, 2)
span_gemm_kernel(const float* __restrict__ A,      // hidden [8192,256]
                 const float* __restrict__ W,      // [T,H,2H] = [1024,512]
                 const float* __restrict__ bias)   // [T,H] = [1024]
{
    __shared__ float As[BK][BM + PAD];
    __shared__ float Bs[BK][BN + PAD];

    const int tid = threadIdx.x;
    const int tx  = tid & 15;
    const int ty  = tid >> 4;

    const int m0 = blockIdx.y * BM;
    const int j0 = blockIdx.x * BN;
    const int pq = j0 >> 10;                        // 0 = start-half, 1 = end-half

    // Wt row j (K-contiguous): W + (j & 1023)*512 + pq*256
    const float* Abase = A + (size_t)m0 * KDIM;
    const float* Bbase = W + (size_t)(j0 - (pq << 10)) * (2 * HID) + pq * HID;

    const int lr = tid >> 2;          // 0..63
    const int lc = (tid & 3) << 2;    // 0,4,8,12

    float acc[TM][TN];
#pragma unroll
    for (int i = 0; i < TM; i++)
#pragma unroll
        for (int j = 0; j < TN; j++) acc[i][j] = 0.f;

    for (int k0 = 0; k0 < KDIM; k0 += BK) {
        float4 a0 = *(const float4*)(Abase + (size_t)lr        * KDIM      + k0 + lc);
        float4 a1 = *(const float4*)(Abase + (size_t)(lr + 64) * KDIM      + k0 + lc);
        float4 b0 = *(const float4*)(Bbase + (size_t)lr        * (2 * HID) + k0 + lc);
        float4 b1 = *(const float4*)(Bbase + (size_t)(lr + 64) * (2 * HID) + k0 + lc);

        __syncthreads();   // previous iteration's smem reads complete
        As[lc + 0][lr]      = a0.x; As[lc + 1][lr]      = a0.y;
        As[lc + 2][lr]      = a0.z; As[lc + 3][lr]      = a0.w;
        As[lc + 0][lr + 64] = a1.x; As[lc + 1][lr + 64] = a1.y;
        As[lc + 2][lr + 64] = a1.z; As[lc + 3][lr + 64] = a1.w;
        Bs[lc + 0][lr]      = b0.x; Bs[lc + 1][lr]      = b0.y;
        Bs[lc + 2][lr]      = b0.z; Bs[lc + 3][lr]      = b0.w;
        Bs[lc + 0][lr + 64] = b1.x; Bs[lc + 1][lr + 64] = b1.y;
        Bs[lc + 2][lr + 64] = b1.z; Bs[lc + 3][lr + 64] = b1.w;
        __syncthreads();

#pragma unroll
        for (int kk = 0; kk < BK; kk++) {
            float4 ra0 = *(const float4*)&As[kk][ty * TM];
            float4 ra1 = *(const float4*)&As[kk][ty * TM + 4];
            float4 rb0 = *(const float4*)&Bs[kk][tx * TN];
            float4 rb1 = *(const float4*)&Bs[kk][tx * TN + 4];
            float ra[8] = {ra0.x, ra0.y, ra0.z, ra0.w, ra1.x, ra1.y, ra1.z, ra1.w};
            float rb[8] = {rb0.x, rb0.y, rb0.z, rb0.w, rb1.x, rb1.y, rb1.z, rb1.w};
#pragma unroll
            for (int i = 0; i < TM; i++)
#pragma unroll
                for (int j = 0; j < TN; j++)
                    acc[i][j] = fmaf(ra[i], rb[j], acc[i][j]);
        }
    }

    // Fold bias into the P half (pq==0): bias[j] = b[t*256+h] for j<1024.
    float4 bv0 = make_float4(0.f, 0.f, 0.f, 0.f);
    float4 bv1 = make_float4(0.f, 0.f, 0.f, 0.f);
    if (pq == 0) {
        bv0 = *(const float4*)(bias + j0 + tx * TN);
        bv1 = *(const float4*)(bias + j0 + tx * TN + 4);
    }

    float* Cbase = g_PQ + (size_t)(m0 + ty * TM) * NCOL + j0 + tx * TN;
#pragma unroll
    for (int i = 0; i < TM; i++) {
        float4 o0 = make_float4(acc[i][0] + bv0.x, acc[i][1] + bv0.y,
                                acc[i][2] + bv0.z, acc[i][3] + bv0.w);
        float4 o1 = make_float4(acc[i][4] + bv1.x, acc[i][5] + bv1.y,
                                acc[i][6] + bv1.z, acc[i][7] + bv1.w);
        *(float4*)(Cbase + (size_t)i * NCOL)     = o0;
        *(float4*)(Cbase + (size_t)i * NCOL + 4) = o1;
    }
}

// ---------------------------- Expansion ------------------------------------
// One block per (span n, batch b): 256 threads cover all T*H = 1024 outputs
// (col = t*256+h). out row index = (b*N + n)*T + t, so flat offset is
// (b*N + n)*1024 + col. P/Q rows are L2-hot (each reused by <=12 spans).
__global__ void __launch_bounds__(256)
span_expand_kernel(float* __restrict__ out)
{
    const int n = blockIdx.x;
    const int b = blockIdx.y;

    int s, e;
    if (n < NFULL) {
        s = n / 12;
        e = s + (n - s * 12);
    } else {                       // tail: s = 1013..1023, counts 11..1
        int m = n - NFULL;
        s = 1013;
        int c = 11;
        while (m >= c) { m -= c; --c; ++s; }
        e = s + m;
    }

    const int col = threadIdx.x << 2;   // 0..1020, step 4

    const float4 p = __ldg((const float4*)(g_PQ + (size_t)(b * SEQ + s) * NCOL + col));
    const float4 q = __ldg((const float4*)(g_PQ + (size_t)(b * SEQ + e) * NCOL + 1024 + col));
    float4 o = make_float4(p.x + q.x, p.y + q.y, p.z + q.z, p.w + q.w);

    // streaming store: output is never re-read, keep PQ resident in L2
    __stcs((float4*)(out + ((size_t)b * NSPAN + n) * (NT * HID) + col), o);
}

// ---------------------------------------------------------------------------
extern "C" void kernel_launch(void* const* d_in, const int* in_sizes, int n_in,
                              void* d_out, int out_size)
{
    const float* hidden = (const float*)d_in[0];   // [8,1024,256] f32
    const float* W      = (const float*)d_in[1];   // [4,256,512]  f32
    const float* bias   = (const float*)d_in[2];   // [4,256]      f32
    // d_in[3] = max_span_length (constant 12, baked into the index math)
    float* out = (float*)d_out;                    // [8, 48888, 256] f32

    dim3 ggrid(NCOL / BN, MROWS / BM);             // (16, 64)
    span_gemm_kernel<<<ggrid, 256>>>(hidden, W, bias);

    dim3 egrid(NSPAN, NBATCH);                     // (12222, 8)
    span_expand_kernel<<<egrid, 256>>>(out);
}

// round 16
// speedup vs baseline: 1.6907x; 1.6907x over previous
#include <cuda_runtime.h>
#include <cuda_bf16.h>
#include <cstdint>

// ---------------------------------------------------------------------------
// SpanRepresentationLayer on GB300.
//
// out[b,(s,e),t,h] = P[b,s,t,h] + Q[b,e,t,h]
//   P[b,s,t,h] = sum_c hid[b,s,c]*W[t,h,c]     + bias[t,h]
//   Q[b,e,t,h] = sum_c hid[b,e,c]*W[t,h,256+c]
//
// Kernel 1: tensor-core GEMM  X[8192,256] x Wt[256,2048] -> PQ (64MB scratch)
//           3xBF16 split precision (hi*hi + hi*lo + lo*hi), fp32 accumulate
//           -> rel error ~2^-16, way under the 1e-3 gate.
// Kernel 2: expansion, one block per (b,s): P row reused for <=12 spans,
//           batched Q loads for MLP, streaming stores.
// ---------------------------------------------------------------------------

#define HID     256
#define SEQ     1024
#define NBATCH  8
#define NT      4
#define NSPAN   12222
#define NFULL   12156       // spans with s <= 1012
#define KDIM    256
#define NCOL    2048        // j = pq*1024 + t*256 + h
#define MROWS   (NBATCH * SEQ)

__device__ float g_PQ[(size_t)MROWS * NCOL];

// ------------------------------ GEMM ---------------------------------------
#define BM 128
#define BN 128
#define BK 32
#define SA 40    // smem k-stride (bf16) with +8 pad -> conflict-free frag loads
#define SB 40

#define MMA_BF16(d, a, b)                                                      \
    asm volatile(                                                              \
        "mma.sync.aligned.m16n8k16.row.col.f32.bf16.bf16.f32 "                 \
        "{%0,%1,%2,%3}, {%4,%5,%6,%7}, {%8,%9}, {%0,%1,%2,%3};\n"              \
        : "+f"(d[0]), "+f"(d[1]), "+f"(d[2]), "+f"(d[3])                       \
        : "r"(a[0]), "r"(a[1]), "r"(a[2]), "r"(a[3]), "r"(b[0]), "r"(b[1]))

__device__ __forceinline__ void split_pair(float x, float y,
                                           uint32_t& h, uint32_t& l)
{
    __nv_bfloat16 hx = __float2bfloat16(x);
    __nv_bfloat16 hy = __float2bfloat16(y);
    __nv_bfloat16 lx = __float2bfloat16(x - __bfloat162float(hx));
    __nv_bfloat16 ly = __float2bfloat16(y - __bfloat162float(hy));
    h = ((uint32_t)__bfloat16_as_ushort(hy) << 16) | (uint32_t)__bfloat16_as_ushort(hx);
    l = ((uint32_t)__bfloat16_as_ushort(ly) << 16) | (uint32_t)__bfloat16_as_ushort(lx);
}

__global__ void __launch_bounds__(256)
span_gemm_kernel(const float* __restrict__ A,      // hidden [8192,256]
                 const float* __restrict__ W,      // [1024,512]
                 const float* __restrict__ bias)   // [1024]
{
    __shared__ __align__(16) unsigned short As_hi[BM * SA];
    __shared__ __align__(16) unsigned short As_lo[BM * SA];
    __shared__ __align__(16) unsigned short Bs_hi[BN * SB];
    __shared__ __align__(16) unsigned short Bs_lo[BN * SB];

    const int tid  = threadIdx.x;
    const int lane = tid & 31;
    const int warp = tid >> 5;
    const int warp_m = warp >> 2;      // 0..1  (64 rows each)
    const int warp_n = warp & 3;       // 0..3  (32 cols each)
    const int qr = lane >> 2;          // 0..7
    const int qc = (lane & 3) * 2;     // 0,2,4,6

    const int m0 = blockIdx.y * BM;
    const int j0 = blockIdx.x * BN;
    const int pq = j0 >> 10;

    // staging: thread loads 16 consecutive floats of one row
    const int lrow  = tid >> 1;        // 0..127
    const int lhalf = (tid & 1) * 16;  // k offset (floats)

    const float* ag = A + (size_t)(m0 + lrow) * KDIM + lhalf;
    const float* bg = W + (size_t)(j0 - (pq << 10) + lrow) * (2 * HID)
                        + pq * HID + lhalf;

    float d[4][4][4];
#pragma unroll
    for (int mt = 0; mt < 4; mt++)
#pragma unroll
        for (int nt = 0; nt < 4; nt++)
#pragma unroll
            for (int i = 0; i < 4; i++) d[mt][nt][i] = 0.f;

    for (int kt = 0; kt < KDIM / BK; kt++) {
        float4 va[4], vb[4];
#pragma unroll
        for (int v = 0; v < 4; v++) {
            va[v] = *(const float4*)(ag + kt * BK + v * 4);
            vb[v] = *(const float4*)(bg + kt * BK + v * 4);
        }

        __syncthreads();   // prior iteration's smem reads complete
#pragma unroll
        for (int v = 0; v < 4; v++) {
            uint32_t h0, l0, h1, l1;
            int ka = lrow * SA + lhalf + v * 4;
            split_pair(va[v].x, va[v].y, h0, l0);
            split_pair(va[v].z, va[v].w, h1, l1);
            *(uint32_t*)&As_hi[ka]     = h0;  *(uint32_t*)&As_lo[ka]     = l0;
            *(uint32_t*)&As_hi[ka + 2] = h1;  *(uint32_t*)&As_lo[ka + 2] = l1;
            int kb = lrow * SB + lhalf + v * 4;
            split_pair(vb[v].x, vb[v].y, h0, l0);
            split_pair(vb[v].z, vb[v].w, h1, l1);
            *(uint32_t*)&Bs_hi[kb]     = h0;  *(uint32_t*)&Bs_lo[kb]     = l0;
            *(uint32_t*)&Bs_hi[kb + 2] = h1;  *(uint32_t*)&Bs_lo[kb + 2] = l1;
        }
        __syncthreads();

#pragma unroll
        for (int ks = 0; ks < BK; ks += 16) {
            uint32_t ah[4][4], al[4][4], bh[4][2], bl[4][2];
#pragma unroll
            for (int mt = 0; mt < 4; mt++) {
                int base = (warp_m * 64 + mt * 16 + qr) * SA + ks + qc;
                ah[mt][0] = *(const uint32_t*)&As_hi[base];
                ah[mt][1] = *(const uint32_t*)&As_hi[base + 8 * SA];
                ah[mt][2] = *(const uint32_t*)&As_hi[base + 8];
                ah[mt][3] = *(const uint32_t*)&As_hi[base + 8 * SA + 8];
                al[mt][0] = *(const uint32_t*)&As_lo[base];
                al[mt][1] = *(const uint32_t*)&As_lo[base + 8 * SA];
                al[mt][2] = *(const uint32_t*)&As_lo[base + 8];
                al[mt][3] = *(const uint32_t*)&As_lo[base + 8 * SA + 8];
            }
#pragma unroll
            for (int nt = 0; nt < 4; nt++) {
                int base = (warp_n * 32 + nt * 8 + qr) * SB + ks + qc;
                bh[nt][0] = *(const uint32_t*)&Bs_hi[base];
                bh[nt][1] = *(const uint32_t*)&Bs_hi[base + 8];
                bl[nt][0] = *(const uint32_t*)&Bs_lo[base];
                bl[nt][1] = *(const uint32_t*)&Bs_lo[base + 8];
            }
#pragma unroll
            for (int mt = 0; mt < 4; mt++)
#pragma unroll
                for (int nt = 0; nt < 4; nt++) {
                    MMA_BF16(d[mt][nt], ah[mt], bh[nt]);
                    MMA_BF16(d[mt][nt], ah[mt], bl[nt]);
                    MMA_BF16(d[mt][nt], al[mt], bh[nt]);
                }
        }
    }

    // epilogue: bias folded into P half (pq==0)
#pragma unroll
    for (int mt = 0; mt < 4; mt++) {
        int r0 = m0 + warp_m * 64 + mt * 16 + qr;
#pragma unroll
        for (int nt = 0; nt < 4; nt++) {
            int cl = j0 + warp_n * 32 + nt * 8 + qc;
            float bx = 0.f, by = 0.f;
            if (pq == 0) {
                float2 bv = *(const float2*)(bias + cl);
                bx = bv.x; by = bv.y;
            }
            *(float2*)(g_PQ + (size_t)r0 * NCOL + cl) =
                make_float2(d[mt][nt][0] + bx, d[mt][nt][1] + by);
            *(float2*)(g_PQ + (size_t)(r0 + 8) * NCOL + cl) =
                make_float2(d[mt][nt][2] + bx, d[mt][nt][3] + by);
        }
    }
}

// ---------------------------- Expansion ------------------------------------
// Block per (b, s): P row loaded once, up to 12 Q rows loaded in a batch
// (MLP), 12 streaming output stores. PQ is L2-resident (64MB < 126MB L2).
__global__ void __launch_bounds__(256)
span_expand_kernel(float* __restrict__ out)
{
    const int s = blockIdx.x;
    const int b = blockIdx.y;
    const int nspan = min(12, SEQ - s);

    size_t n0;
    if (s < 1013) n0 = (size_t)s * 12;
    else {
        int dd = s - 1013;
        n0 = (size_t)NFULL + 11 * dd - (dd * (dd - 1)) / 2;
    }

    const int col = threadIdx.x << 2;
    const float* base = g_PQ + ((size_t)b * SEQ + s) * NCOL + col;

    const float4 p = __ldg((const float4*)base);
    const float* qb = base + 1024;
    float* ob = out + ((size_t)b * NSPAN + n0) * (NT * HID) + col;

    if (nspan == 12) {
        float4 q[12];
#pragma unroll
        for (int i = 0; i < 12; i++)
            q[i] = __ldg((const float4*)(qb + (size_t)i * NCOL));
#pragma unroll
        for (int i = 0; i < 12; i++) {
            float4 o = make_float4(p.x + q[i].x, p.y + q[i].y,
                                   p.z + q[i].z, p.w + q[i].w);
            __stcs((float4*)(ob + (size_t)i * (NT * HID)), o);
        }
    } else {
        for (int i = 0; i < nspan; i++) {
            float4 q = __ldg((const float4*)(qb + (size_t)i * NCOL));
            float4 o = make_float4(p.x + q.x, p.y + q.y, p.z + q.z, p.w + q.w);
            __stcs((float4*)(ob + (size_t)i * (NT * HID)), o);
        }
    }
}

// ---------------------------------------------------------------------------
extern "C" void kernel_launch(void* const* d_in, const int* in_sizes, int n_in,
                              void* d_out, int out_size)
{
    const float* hidden = (const float*)d_in[0];
    const float* W      = (const float*)d_in[1];
    const float* bias   = (const float*)d_in[2];
    float* out = (float*)d_out;

    dim3 ggrid(NCOL / BN, MROWS / BM);   // (16, 64)
    span_gemm_kernel<<<ggrid, 256>>>(hidden, W, bias);

    dim3 egrid(SEQ, NBATCH);             // (1024, 8)
    span_expand_kernel<<<egrid, 256>>>(out);
}

// round 17
// speedup vs baseline: 1.7450x; 1.0321x over previous
#include <cuda_runtime.h>
#include <cuda_bf16.h>
#include <cstdint>

// ---------------------------------------------------------------------------
// SpanRepresentationLayer on GB300.
//
// out[b,(s,e),t,h] = P[b,s,t,h] + Q[b,e,t,h]
//   P = hid @ W[:,:, :256]^T + bias ; Q = hid @ W[:,:, 256:]^T
//
// K0: split hidden + Wt into bf16 hi/lo scratch (3xBF16 precision scheme)
// K1: cp.async double-buffered tensor-core GEMM X[8192,256] x Wt^T[256,2048]
//     3 MMA passes (hi*hi + hi*lo + lo*hi), fp32 accum -> err ~2^-16
// K2: expansion, one block per (b,s): P row reused for <=12 spans.
// ---------------------------------------------------------------------------

#define HID     256
#define SEQ     1024
#define NBATCH  8
#define NT      4
#define NSPAN   12222
#define NFULL   12156
#define KDIM    256
#define NCOL    2048
#define MROWS   8192
#define NJ      2048

__device__ float        g_PQ [(size_t)MROWS * NCOL];
__device__ __nv_bfloat16 g_Ahi[(size_t)MROWS * KDIM];
__device__ __nv_bfloat16 g_Alo[(size_t)MROWS * KDIM];
__device__ __nv_bfloat16 g_Bhi[(size_t)NJ    * KDIM];
__device__ __nv_bfloat16 g_Blo[(size_t)NJ    * KDIM];

// ------------------------- K0: precision split ------------------------------
__global__ void __launch_bounds__(256)
split_kernel(const float* __restrict__ A, const float* __restrict__ W)
{
    const int A4 = MROWS * KDIM / 4;   // 524288 float4s
    const int B4 = NJ * KDIM / 4;      // 131072 float4s
    int i = blockIdx.x * 256 + threadIdx.x;

    float4 v;
    __nv_bfloat16 *hi, *lo;
    size_t off;
    if (i < A4) {
        v = __ldg((const float4*)A + i);
        hi = g_Ahi; lo = g_Alo; off = (size_t)i * 4;
    } else if (i < A4 + B4) {
        int j4 = i - A4;
        int j = (j4 * 4) / KDIM;                  // Wt row: j = pq*1024 + t*256 + h
        int k = (j4 * 4) % KDIM;
        v = __ldg((const float4*)(W + (size_t)(j & 1023) * 512 + (j >> 10) * HID + k));
        hi = g_Bhi; lo = g_Blo; off = (size_t)j4 * 4;
    } else return;

    __nv_bfloat16 h[4], l[4];
    float f[4] = {v.x, v.y, v.z, v.w};
#pragma unroll
    for (int t = 0; t < 4; t++) {
        h[t] = __float2bfloat16(f[t]);
        l[t] = __float2bfloat16(f[t] - __bfloat162float(h[t]));
    }
    *(uint2*)(hi + off) = *(uint2*)h;
    *(uint2*)(lo + off) = *(uint2*)l;
}

// ------------------------------ K1: GEMM ------------------------------------
#define BK 32
#define SA 40                         // padded k-stride (bf16 elems)
#define STG (128 * SA)                // elems per stage per array

#define MMA_BF16(d, a, b)                                                      \
    asm volatile(                                                              \
        "mma.sync.aligned.m16n8k16.row.col.f32.bf16.bf16.f32 "                 \
        "{%0,%1,%2,%3}, {%4,%5,%6,%7}, {%8,%9}, {%0,%1,%2,%3};\n"              \
        : "+f"(d[0]), "+f"(d[1]), "+f"(d[2]), "+f"(d[3])                       \
        : "r"(a[0]), "r"(a[1]), "r"(a[2]), "r"(a[3]), "r"(b[0]), "r"(b[1]))

__device__ __forceinline__ void cp16(uint32_t dst, const void* src)
{
    asm volatile("cp.async.cg.shared.global [%0], [%1], 16;\n"
                 :: "r"(dst), "l"(src));
}

__global__ void __launch_bounds__(256)
span_gemm_kernel(const float* __restrict__ bias)
{
    extern __shared__ __nv_bfloat16 smem[];
    __nv_bfloat16* Ah = smem;               // [2][STG]
    __nv_bfloat16* Al = smem + 2 * STG;
    __nv_bfloat16* Bh = smem + 4 * STG;
    __nv_bfloat16* Bl = smem + 6 * STG;

    const int tid  = threadIdx.x;
    const int lane = tid & 31;
    const int warp = tid >> 5;
    const int warp_m = warp >> 2;           // 0..1 (64 rows)
    const int warp_n = warp & 3;            // 0..3 (32 cols)
    const int qr = lane >> 2;
    const int qc = (lane & 3) * 2;

    const int m0 = blockIdx.y * 128;
    const int j0 = blockIdx.x * 128;
    const int pq = j0 >> 10;

    // cp.async staging: thread covers 32 contiguous bytes (2x16B) of one row
    const int lrow = tid >> 1;
    const int lcb  = (tid & 1) * 16;        // bf16 elem offset

    const __nv_bfloat16* gAh = g_Ahi + (size_t)(m0 + lrow) * KDIM + lcb;
    const __nv_bfloat16* gAl = g_Alo + (size_t)(m0 + lrow) * KDIM + lcb;
    const __nv_bfloat16* gBh = g_Bhi + (size_t)(j0 + lrow) * KDIM + lcb;
    const __nv_bfloat16* gBl = g_Blo + (size_t)(j0 + lrow) * KDIM + lcb;

    const uint32_t sb  = (uint32_t)__cvta_generic_to_shared(smem);
    const uint32_t dAh = sb + (uint32_t)(lrow * SA + lcb) * 2;
    const uint32_t dAl = dAh + 4  * STG;    // byte offsets (elems*2)
    const uint32_t dBh = dAh + 8  * STG;
    const uint32_t dBl = dAh + 12 * STG;

#define LOADSTAGE(buf, kt) do {                                                \
        int      go = (kt) * BK;                                               \
        uint32_t so = (uint32_t)(buf) * (STG * 2);                             \
        cp16(dAh + so, gAh + go); cp16(dAh + so + 16, gAh + go + 8);           \
        cp16(dAl + so, gAl + go); cp16(dAl + so + 16, gAl + go + 8);           \
        cp16(dBh + so, gBh + go); cp16(dBh + so + 16, gBh + go + 8);           \
        cp16(dBl + so, gBl + go); cp16(dBl + so + 16, gBl + go + 8);           \
        asm volatile("cp.async.commit_group;\n");                              \
    } while (0)

    float d[4][4][4];
#pragma unroll
    for (int mt = 0; mt < 4; mt++)
#pragma unroll
        for (int nt = 0; nt < 4; nt++)
#pragma unroll
            for (int i = 0; i < 4; i++) d[mt][nt][i] = 0.f;

    LOADSTAGE(0, 0);

    for (int kt = 0; kt < KDIM / BK; kt++) {
        if (kt + 1 < KDIM / BK) LOADSTAGE((kt + 1) & 1, kt + 1);
        else asm volatile("cp.async.commit_group;\n");
        asm volatile("cp.async.wait_group 1;\n");
        __syncthreads();

        const __nv_bfloat16* cAh = Ah + (kt & 1) * STG;
        const __nv_bfloat16* cAl = Al + (kt & 1) * STG;
        const __nv_bfloat16* cBh = Bh + (kt & 1) * STG;
        const __nv_bfloat16* cBl = Bl + (kt & 1) * STG;

#pragma unroll
        for (int ks = 0; ks < BK; ks += 16) {
            uint32_t ah[4][4], al[4][4], bh[4][2], bl[4][2];
#pragma unroll
            for (int mt = 0; mt < 4; mt++) {
                int base = (warp_m * 64 + mt * 16 + qr) * SA + ks + qc;
                ah[mt][0] = *(const uint32_t*)&cAh[base];
                ah[mt][1] = *(const uint32_t*)&cAh[base + 8 * SA];
                ah[mt][2] = *(const uint32_t*)&cAh[base + 8];
                ah[mt][3] = *(const uint32_t*)&cAh[base + 8 * SA + 8];
                al[mt][0] = *(const uint32_t*)&cAl[base];
                al[mt][1] = *(const uint32_t*)&cAl[base + 8 * SA];
                al[mt][2] = *(const uint32_t*)&cAl[base + 8];
                al[mt][3] = *(const uint32_t*)&cAl[base + 8 * SA + 8];
            }
#pragma unroll
            for (int nt = 0; nt < 4; nt++) {
                int base = (warp_n * 32 + nt * 8 + qr) * SA + ks + qc;
                bh[nt][0] = *(const uint32_t*)&cBh[base];
                bh[nt][1] = *(const uint32_t*)&cBh[base + 8];
                bl[nt][0] = *(const uint32_t*)&cBl[base];
                bl[nt][1] = *(const uint32_t*)&cBl[base + 8];
            }
#pragma unroll
            for (int mt = 0; mt < 4; mt++)
#pragma unroll
                for (int nt = 0; nt < 4; nt++) {
                    MMA_BF16(d[mt][nt], ah[mt], bh[nt]);
                    MMA_BF16(d[mt][nt], ah[mt], bl[nt]);
                    MMA_BF16(d[mt][nt], al[mt], bh[nt]);
                }
        }
        __syncthreads();
    }

    // epilogue: bias folded into P half (pq==0)
#pragma unroll
    for (int mt = 0; mt < 4; mt++) {
        int r0 = m0 + warp_m * 64 + mt * 16 + qr;
#pragma unroll
        for (int nt = 0; nt < 4; nt++) {
            int cl = j0 + warp_n * 32 + nt * 8 + qc;
            float bx = 0.f, by = 0.f;
            if (pq == 0) {
                float2 bv = *(const float2*)(bias + cl);
                bx = bv.x; by = bv.y;
            }
            *(float2*)(g_PQ + (size_t)r0 * NCOL + cl) =
                make_float2(d[mt][nt][0] + bx, d[mt][nt][1] + by);
            *(float2*)(g_PQ + (size_t)(r0 + 8) * NCOL + cl) =
                make_float2(d[mt][nt][2] + bx, d[mt][nt][3] + by);
        }
    }
}

// ---------------------------- K2: expansion ---------------------------------
__global__ void __launch_bounds__(256)
span_expand_kernel(float* __restrict__ out)
{
    const int s = blockIdx.x;
    const int b = blockIdx.y;
    const int nspan = min(12, SEQ - s);

    size_t n0;
    if (s < 1013) n0 = (size_t)s * 12;
    else {
        int dd = s - 1013;
        n0 = (size_t)NFULL + 11 * dd - (dd * (dd - 1)) / 2;
    }

    const int col = threadIdx.x << 2;
    const float* base = g_PQ + ((size_t)b * SEQ + s) * NCOL + col;

    const float4 p = __ldg((const float4*)base);
    const float* qb = base + 1024;
    float* ob = out + ((size_t)b * NSPAN + n0) * (NT * HID) + col;

    if (nspan == 12) {
        float4 q[12];
#pragma unroll
        for (int i = 0; i < 12; i++)
            q[i] = __ldg((const float4*)(qb + (size_t)i * NCOL));
#pragma unroll
        for (int i = 0; i < 12; i++) {
            float4 o = make_float4(p.x + q[i].x, p.y + q[i].y,
                                   p.z + q[i].z, p.w + q[i].w);
            __stcs((float4*)(ob + (size_t)i * (NT * HID)), o);
        }
    } else {
        for (int i = 0; i < nspan; i++) {
            float4 q = __ldg((const float4*)(qb + (size_t)i * NCOL));
            float4 o = make_float4(p.x + q.x, p.y + q.y, p.z + q.z, p.w + q.w);
            __stcs((float4*)(ob + (size_t)i * (NT * HID)), o);
        }
    }
}

// ---------------------------------------------------------------------------
extern "C" void kernel_launch(void* const* d_in, const int* in_sizes, int n_in,
                              void* d_out, int out_size)
{
    const float* hidden = (const float*)d_in[0];
    const float* W      = (const float*)d_in[1];
    const float* bias   = (const float*)d_in[2];
    float* out = (float*)d_out;

    const int SMEM_BYTES = 8 * STG * 2;   // 81920
    cudaFuncSetAttribute(span_gemm_kernel,
                         cudaFuncAttributeMaxDynamicSharedMemorySize, SMEM_BYTES);

    int split_blocks = (MROWS * KDIM / 4 + NJ * KDIM / 4 + 255) / 256;
    split_kernel<<<split_blocks, 256>>>(hidden, W);

    dim3 ggrid(NCOL / 128, MROWS / 128);   // (16, 64)
    span_gemm_kernel<<<ggrid, 256, SMEM_BYTES>>>(bias);

    dim3 egrid(SEQ, NBATCH);               // (1024, 8)
    span_expand_kernel<<<egrid, 256>>>(out);
}